// round 1
// baseline (speedup 1.0000x reference)
#include <cuda_runtime.h>

#define Nn 10000
#define Ee 100000
#define Cc 32
#define Gg 64
#define BN_EPS 1e-5f

// ---- scratch (static device globals; no runtime allocation) ----
__device__ float g_T[(size_t)Nn * Cc * Cc];   // 40.96 MB per-node transformed weights
__device__ float g_xb[Nn * Cc];               // b2 contribution per node
__device__ float g_agg[Nn * Cc];              // scatter-sum accumulator
__device__ float g_h1[Nn * Cc];               // layer-1 output
__device__ float g_h2[Nn * Cc];               // layer-2 output
__device__ float g_deg[Nn];                   // in-degree
__device__ float g_pool[Gg * Cc];
__device__ float g_pcnt[Gg];

// ---- zero kernels (graph-capturable, no memset API needed) ----
__global__ void k_zero_all() {
    int i = blockIdx.x * blockDim.x + threadIdx.x;
    if (i < Nn * Cc) g_agg[i] = 0.f;
    if (i < Nn)      g_deg[i] = 0.f;
    if (i < Gg * Cc) g_pool[i] = 0.f;
    if (i < Gg)      g_pcnt[i] = 0.f;
}
__global__ void k_zero_agg() {
    int i = blockIdx.x * blockDim.x + threadIdx.x;
    if (i < Nn * Cc) g_agg[i] = 0.f;
}

// ---- in-degree (same for both layers) ----
__global__ void k_deg(const int* __restrict__ ei) {
    int e = blockIdx.x * blockDim.x + threadIdx.x;
    if (e < Ee) atomicAdd(&g_deg[ei[Ee + e]], 1.f);
}

// ---- xb[n,o] = sum_i x[n,i] * b2[i*C+o] ----
__global__ void k_xb(const float* __restrict__ x, const float* __restrict__ b2) {
    int t = blockIdx.x * blockDim.x + threadIdx.x;
    if (t >= Nn * Cc) return;
    int n = t >> 5, o = t & 31;
    const float* xr = x + n * Cc;
    float acc = 0.f;
#pragma unroll
    for (int i = 0; i < Cc; i++) acc += xr[i] * b2[i * Cc + o];
    g_xb[t] = acc;
}

// ---- T[n,k,o] = sum_i x[n,i] * w2[k, i*C+o] ----
// block = 1024 threads, thread owns (k,o) = (tid>>5, tid&31); w2 column held in 32 regs.
__global__ void __launch_bounds__(1024, 1)
k_T(const float* __restrict__ x, const float* __restrict__ w2) {
    int k = threadIdx.x >> 5, o = threadIdx.x & 31;
    float w[32];
#pragma unroll
    for (int i = 0; i < 32; i++) w[i] = w2[k * 1024 + i * 32 + o];

    __shared__ float xs[32][32];
    int npb = (Nn + gridDim.x - 1) / gridDim.x;
    int n0 = blockIdx.x * npb;
    int n1 = min(n0 + npb, Nn);
    for (int nb = n0; nb < n1; nb += 32) {
        int cnt = min(32, n1 - nb);
        if ((int)threadIdx.x < cnt * 32)
            ((float*)xs)[threadIdx.x] = x[nb * 32 + threadIdx.x];
        __syncthreads();
        for (int j = 0; j < cnt; j++) {
            float acc = 0.f;
#pragma unroll
            for (int i = 0; i < 32; i++) acc += xs[j][i] * w[i];
            g_T[(size_t)(nb + j) * 1024 + threadIdx.x] = acc;  // k*32+o == tid
        }
        __syncthreads();
    }
}

// ---- edge kernel: one warp per edge, lane = output channel o ----
// msg[e,o] = xb[src,o] + sum_k relu(ea@w1+b1)[k] * T[src,k,o]; atomic scatter to dst.
__global__ void k_edge(const float* __restrict__ ea, const int* __restrict__ ei,
                       const float* __restrict__ w1, const float* __restrict__ b1) {
    int gtid = blockIdx.x * blockDim.x + threadIdx.x;
    int e = gtid >> 5;
    if (e >= Ee) return;
    int o = threadIdx.x & 31;
    int src = __ldg(&ei[e]);
    int dst = __ldg(&ei[Ee + e]);
    float4 a = __ldg((const float4*)ea + e);
    float h = b1[o] + a.x * w1[o] + a.y * w1[32 + o] + a.z * w1[64 + o] + a.w * w1[96 + o];
    h = fmaxf(h, 0.f);

    const float* Tp = g_T + (size_t)src * 1024 + o;
    float acc = g_xb[src * 32 + o];
#pragma unroll
    for (int k = 0; k < 32; k++)
        acc += __shfl_sync(0xffffffffu, h, k) * Tp[k * 32];

    atomicAdd(&g_agg[dst * 32 + o], acc);
}

// ---- node update: mean-agg + root matmul + bias + BN + ReLU ----
__global__ void k_node(const float* __restrict__ xin, const float* __restrict__ root,
                       const float* __restrict__ bias,
                       const float* __restrict__ bg, const float* __restrict__ bb,
                       const float* __restrict__ bm, const float* __restrict__ bv,
                       float* __restrict__ out) {
    int t = blockIdx.x * blockDim.x + threadIdx.x;
    if (t >= Nn * Cc) return;
    int n = t >> 5, o = t & 31;
    float val = g_agg[t] / fmaxf(g_deg[n], 1.f);
    const float* xr = xin + n * Cc;
#pragma unroll
    for (int i = 0; i < Cc; i++) val += xr[i] * root[i * Cc + o];
    val += bias[o];
    val = (val - bm[o]) * rsqrtf(bv[o] + BN_EPS) * bg[o] + bb[o];
    out[t] = fmaxf(val, 0.f);
}

// ---- global mean pool (atomic scatter over graphs) ----
__global__ void k_pool(const int* __restrict__ batch) {
    int t = blockIdx.x * blockDim.x + threadIdx.x;
    if (t >= Nn * Cc) return;
    int n = t >> 5, o = t & 31;
    int gph = batch[n];
    atomicAdd(&g_pool[gph * Cc + o], g_h2[t]);
    if (o == 0) atomicAdd(&g_pcnt[gph], 1.f);
}

// ---- readout MLP: one thread per graph (tiny) ----
__global__ void k_readout(const float* __restrict__ r1w, const float* __restrict__ r1b,
                          const float* __restrict__ r2w, const float* __restrict__ r2b,
                          float* __restrict__ out) {
    int gph = blockIdx.x * blockDim.x + threadIdx.x;
    if (gph >= Gg) return;
    float c = fmaxf(g_pcnt[gph], 1.f);
    float p[Cc];
#pragma unroll
    for (int o = 0; o < Cc; o++) p[o] = g_pool[gph * Cc + o] / c;
    float res = r2b[0];
#pragma unroll
    for (int j = 0; j < 16; j++) {
        float hid = r1b[j];
#pragma unroll
        for (int o = 0; o < Cc; o++) hid += p[o] * r1w[o * 16 + j];
        res += fmaxf(hid, 0.f) * r2w[j];
    }
    out[gph] = res;
}

extern "C" void kernel_launch(void* const* d_in, const int* in_sizes, int n_in,
                              void* d_out, int out_size) {
    const float* x     = (const float*)d_in[0];
    const float* ea    = (const float*)d_in[1];
    const float* e1w1  = (const float*)d_in[2];
    const float* e1b1  = (const float*)d_in[3];
    const float* e1w2  = (const float*)d_in[4];
    const float* e1b2  = (const float*)d_in[5];
    const float* root1 = (const float*)d_in[6];
    const float* bias1 = (const float*)d_in[7];
    const float* e2w1  = (const float*)d_in[8];
    const float* e2b1  = (const float*)d_in[9];
    const float* e2w2  = (const float*)d_in[10];
    const float* e2b2  = (const float*)d_in[11];
    const float* root2 = (const float*)d_in[12];
    const float* bias2 = (const float*)d_in[13];
    const float* bn1g  = (const float*)d_in[14];
    const float* bn1b  = (const float*)d_in[15];
    const float* bn1m  = (const float*)d_in[16];
    const float* bn1v  = (const float*)d_in[17];
    const float* bn2g  = (const float*)d_in[18];
    const float* bn2b  = (const float*)d_in[19];
    const float* bn2m  = (const float*)d_in[20];
    const float* bn2v  = (const float*)d_in[21];
    const float* r1w   = (const float*)d_in[22];
    const float* r1b   = (const float*)d_in[23];
    const float* r2w   = (const float*)d_in[24];
    const float* r2b   = (const float*)d_in[25];
    const int*   eidx  = (const int*)d_in[26];
    const int*   batch = (const int*)d_in[27];
    float* out = (float*)d_out;

    // device pointers of the scratch symbols (pure query; capture-safe)
    float *p_h1 = nullptr, *p_h2 = nullptr;
    cudaGetSymbolAddress((void**)&p_h1, g_h1);
    cudaGetSymbolAddress((void**)&p_h2, g_h2);

    const int THR = 256;
    const int gNC = (Nn * Cc + THR - 1) / THR;    // 1250 blocks
    const int gE  = (Ee + THR - 1) / THR;
    const int gEW = (Ee * 32) / THR;              // 12500 blocks, warp per edge

    k_zero_all<<<gNC, THR>>>();
    k_deg<<<gE, THR>>>(eidx);

    // layer 1
    k_xb<<<gNC, THR>>>(x, e1b2);
    k_T<<<148, 1024>>>(x, e1w2);
    k_edge<<<gEW, THR>>>(ea, eidx, e1w1, e1b1);
    k_node<<<gNC, THR>>>(x, root1, bias1, bn1g, bn1b, bn1m, bn1v, p_h1);

    // layer 2
    k_zero_agg<<<gNC, THR>>>();
    k_xb<<<gNC, THR>>>(p_h1, e2b2);
    k_T<<<148, 1024>>>(p_h1, e2w2);
    k_edge<<<gEW, THR>>>(ea, eidx, e2w1, e2b1);
    k_node<<<gNC, THR>>>(p_h1, root2, bias2, bn2g, bn2b, bn2m, bn2v, p_h2);

    // pool + readout
    k_pool<<<gNC, THR>>>(batch);
    k_readout<<<1, 64>>>(r1w, r1b, r2w, r2b, out);
}

// round 2
// speedup vs baseline: 1.0045x; 1.0045x over previous
#include <cuda_runtime.h>

#define Nn 10000
#define Ee 100000
#define Cc 32
#define Gg 64
#define BN_EPS 1e-5f

// ---- scratch (static device globals; no runtime allocation) ----
__device__ float g_T[(size_t)Nn * Cc * Cc];   // 40.96 MB per-node transformed weights
__device__ float g_xb[Nn * Cc];               // b2 contribution per node
__device__ float g_agg[Nn * Cc];              // scatter-sum accumulator
__device__ float g_h1[Nn * Cc];               // layer-1 output
__device__ float g_h2[Nn * Cc];               // layer-2 output
__device__ float g_deg[Nn];                   // in-degree
__device__ float g_pool[Gg * Cc];
__device__ float g_pcnt[Gg];

// ---- zero kernels (graph-capturable, no memset API needed) ----
__global__ void k_zero_all() {
    int i = blockIdx.x * blockDim.x + threadIdx.x;
    if (i < Nn * Cc) g_agg[i] = 0.f;
    if (i < Nn)      g_deg[i] = 0.f;
    if (i < Gg * Cc) g_pool[i] = 0.f;
    if (i < Gg)      g_pcnt[i] = 0.f;
}
__global__ void k_zero_agg() {
    int i = blockIdx.x * blockDim.x + threadIdx.x;
    if (i < Nn * Cc) g_agg[i] = 0.f;
}

// ---- in-degree (same for both layers) ----
__global__ void k_deg(const int* __restrict__ ei) {
    int e = blockIdx.x * blockDim.x + threadIdx.x;
    if (e < Ee) atomicAdd(&g_deg[ei[Ee + e]], 1.f);
}

// ---- xb[n,o] = sum_i x[n,i] * b2[i*C+o] ----
__global__ void k_xb(const float* __restrict__ x, const float* __restrict__ b2) {
    int t = blockIdx.x * blockDim.x + threadIdx.x;
    if (t >= Nn * Cc) return;
    int n = t >> 5, o = t & 31;
    const float* xr = x + n * Cc;
    float acc = 0.f;
#pragma unroll
    for (int i = 0; i < Cc; i++) acc += xr[i] * b2[i * Cc + o];
    g_xb[t] = acc;
}

// ---- T[n,k,o] = sum_i x[n,i] * w2[k, i*C+o] ----
// block = 1024 threads, thread owns (k,o) = (tid>>5, tid&31); w2 column held in 32 regs.
__global__ void __launch_bounds__(1024, 1)
k_T(const float* __restrict__ x, const float* __restrict__ w2) {
    int k = threadIdx.x >> 5, o = threadIdx.x & 31;
    float w[32];
#pragma unroll
    for (int i = 0; i < 32; i++) w[i] = w2[k * 1024 + i * 32 + o];

    __shared__ float xs[32][32];
    int npb = (Nn + gridDim.x - 1) / gridDim.x;
    int n0 = blockIdx.x * npb;
    int n1 = min(n0 + npb, Nn);
    for (int nb = n0; nb < n1; nb += 32) {
        int cnt = min(32, n1 - nb);
        if ((int)threadIdx.x < cnt * 32)
            ((float*)xs)[threadIdx.x] = x[nb * 32 + threadIdx.x];
        __syncthreads();
        for (int j = 0; j < cnt; j++) {
            float acc = 0.f;
#pragma unroll
            for (int i = 0; i < 32; i++) acc += xs[j][i] * w[i];
            g_T[(size_t)(nb + j) * 1024 + threadIdx.x] = acc;  // k*32+o == tid
        }
        __syncthreads();
    }
}

// ---- edge kernel: one warp per edge, lane = output channel o ----
// msg[e,o] = xb[src,o] + sum_k relu(ea@w1+b1)[k] * T[src,k,o]; atomic scatter to dst.
__global__ void k_edge(const float* __restrict__ ea, const int* __restrict__ ei,
                       const float* __restrict__ w1, const float* __restrict__ b1) {
    int gtid = blockIdx.x * blockDim.x + threadIdx.x;
    int e = gtid >> 5;
    if (e >= Ee) return;
    int o = threadIdx.x & 31;
    int src = __ldg(&ei[e]);
    int dst = __ldg(&ei[Ee + e]);
    float4 a = __ldg((const float4*)ea + e);
    float h = b1[o] + a.x * w1[o] + a.y * w1[32 + o] + a.z * w1[64 + o] + a.w * w1[96 + o];
    h = fmaxf(h, 0.f);

    const float* Tp = g_T + (size_t)src * 1024 + o;
    float acc = g_xb[src * 32 + o];
#pragma unroll
    for (int k = 0; k < 32; k++)
        acc += __shfl_sync(0xffffffffu, h, k) * Tp[k * 32];

    atomicAdd(&g_agg[dst * 32 + o], acc);
}

// ---- node update: mean-agg + root matmul + bias + BN + ReLU ----
__global__ void k_node(const float* __restrict__ xin, const float* __restrict__ root,
                       const float* __restrict__ bias,
                       const float* __restrict__ bg, const float* __restrict__ bb,
                       const float* __restrict__ bm, const float* __restrict__ bv,
                       float* __restrict__ out) {
    int t = blockIdx.x * blockDim.x + threadIdx.x;
    if (t >= Nn * Cc) return;
    int n = t >> 5, o = t & 31;
    float val = g_agg[t] / fmaxf(g_deg[n], 1.f);
    const float* xr = xin + n * Cc;
#pragma unroll
    for (int i = 0; i < Cc; i++) val += xr[i] * root[i * Cc + o];
    val += bias[o];
    val = (val - bm[o]) * rsqrtf(bv[o] + BN_EPS) * bg[o] + bb[o];
    out[t] = fmaxf(val, 0.f);
}

// ---- global mean pool (atomic scatter over graphs) ----
__global__ void k_pool(const int* __restrict__ batch) {
    int t = blockIdx.x * blockDim.x + threadIdx.x;
    if (t >= Nn * Cc) return;
    int n = t >> 5, o = t & 31;
    int gph = batch[n];
    atomicAdd(&g_pool[gph * Cc + o], g_h2[t]);
    if (o == 0) atomicAdd(&g_pcnt[gph], 1.f);
}

// ---- readout MLP: one thread per graph (tiny) ----
__global__ void k_readout(const float* __restrict__ r1w, const float* __restrict__ r1b,
                          const float* __restrict__ r2w, const float* __restrict__ r2b,
                          float* __restrict__ out) {
    int gph = blockIdx.x * blockDim.x + threadIdx.x;
    if (gph >= Gg) return;
    float c = fmaxf(g_pcnt[gph], 1.f);
    float p[Cc];
#pragma unroll
    for (int o = 0; o < Cc; o++) p[o] = g_pool[gph * Cc + o] / c;
    float res = r2b[0];
#pragma unroll
    for (int j = 0; j < 16; j++) {
        float hid = r1b[j];
#pragma unroll
        for (int o = 0; o < Cc; o++) hid += p[o] * r1w[o * 16 + j];
        res += fmaxf(hid, 0.f) * r2w[j];
    }
    out[gph] = res;
}

extern "C" void kernel_launch(void* const* d_in, const int* in_sizes, int n_in,
                              void* d_out, int out_size) {
    const float* x     = (const float*)d_in[0];
    const float* ea    = (const float*)d_in[1];
    const float* e1w1  = (const float*)d_in[2];
    const float* e1b1  = (const float*)d_in[3];
    const float* e1w2  = (const float*)d_in[4];
    const float* e1b2  = (const float*)d_in[5];
    const float* root1 = (const float*)d_in[6];
    const float* bias1 = (const float*)d_in[7];
    const float* e2w1  = (const float*)d_in[8];
    const float* e2b1  = (const float*)d_in[9];
    const float* e2w2  = (const float*)d_in[10];
    const float* e2b2  = (const float*)d_in[11];
    const float* root2 = (const float*)d_in[12];
    const float* bias2 = (const float*)d_in[13];
    const float* bn1g  = (const float*)d_in[14];
    const float* bn1b  = (const float*)d_in[15];
    const float* bn1m  = (const float*)d_in[16];
    const float* bn1v  = (const float*)d_in[17];
    const float* bn2g  = (const float*)d_in[18];
    const float* bn2b  = (const float*)d_in[19];
    const float* bn2m  = (const float*)d_in[20];
    const float* bn2v  = (const float*)d_in[21];
    const float* r1w   = (const float*)d_in[22];
    const float* r1b   = (const float*)d_in[23];
    const float* r2w   = (const float*)d_in[24];
    const float* r2b   = (const float*)d_in[25];
    const int*   eidx  = (const int*)d_in[26];
    const int*   batch = (const int*)d_in[27];
    float* out = (float*)d_out;

    // device pointers of the scratch symbols (pure query; capture-safe)
    float *p_h1 = nullptr, *p_h2 = nullptr;
    cudaGetSymbolAddress((void**)&p_h1, g_h1);
    cudaGetSymbolAddress((void**)&p_h2, g_h2);

    const int THR = 256;
    const int gNC = (Nn * Cc + THR - 1) / THR;    // 1250 blocks
    const int gE  = (Ee + THR - 1) / THR;
    const int gEW = (Ee * 32) / THR;              // 12500 blocks, warp per edge

    k_zero_all<<<gNC, THR>>>();
    k_deg<<<gE, THR>>>(eidx);

    // layer 1
    k_xb<<<gNC, THR>>>(x, e1b2);
    k_T<<<148, 1024>>>(x, e1w2);
    k_edge<<<gEW, THR>>>(ea, eidx, e1w1, e1b1);
    k_node<<<gNC, THR>>>(x, root1, bias1, bn1g, bn1b, bn1m, bn1v, p_h1);

    // layer 2
    k_zero_agg<<<gNC, THR>>>();
    k_xb<<<gNC, THR>>>(p_h1, e2b2);
    k_T<<<148, 1024>>>(p_h1, e2w2);
    k_edge<<<gEW, THR>>>(ea, eidx, e2w1, e2b1);
    k_node<<<gNC, THR>>>(p_h1, root2, bias2, bn2g, bn2b, bn2m, bn2v, p_h2);

    // pool + readout
    k_pool<<<gNC, THR>>>(batch);
    k_readout<<<1, 64>>>(r1w, r1b, r2w, r2b, out);
}